// round 15
// baseline (speedup 1.0000x reference)
#include <cuda_runtime.h>
#include <cuda_bf16.h>
#include <math.h>
#include <stdint.h>

// Problem dims
#define B_    512
#define NSLOT 128
#define IN_   2048
#define MEMD  64
#define OUT_  2048
#define NC    130
#define CONC  2176

// ---------------- scratch ----------------
__device__ float g_Wcat[IN_ * NC];
__device__ float g_T[B_ * NC];
__device__ __align__(256) __nv_bfloat16 g_Ah[B_ * CONC];
__device__ __align__(256) __nv_bfloat16 g_Al[B_ * CONC];
__device__ __align__(256) __nv_bfloat16 g_Bh[OUT_ * CONC];
__device__ __align__(256) __nv_bfloat16 g_Bl[OUT_ * CONC];
__device__ __align__(256) float g_Cp[3 * B_ * OUT_];   // split-K partials (main x2, tail x1)

// ---------------- helpers ----------------
typedef unsigned long long u64t;
__device__ __forceinline__ u64t pk2(float lo, float hi) {
    u64t r; asm("mov.b64 %0, {%1,%2};" : "=l"(r) : "f"(lo), "f"(hi)); return r;
}
__device__ __forceinline__ void fma2(u64t& d, u64t a, u64t b) {
    asm("fma.rn.f32x2 %0, %1, %2, %3;" : "=l"(d) : "l"(a), "l"(b), "l"(d));
}
__device__ __forceinline__ float2 upk2(u64t v) {
    float lo, hi; asm("mov.b64 {%0,%1}, %2;" : "=f"(lo), "=f"(hi) : "l"(v));
    return make_float2(lo, hi);
}
__device__ __forceinline__ uint32_t smem_u32(const void* p) {
    uint32_t a;
    asm("{ .reg .u64 t; cvta.to.shared.u64 t, %1; cvt.u32.u64 %0, t; }" : "=r"(a) : "l"(p));
    return a;
}
__device__ __forceinline__ void cp16(uint32_t dst, const void* src) {
    asm volatile("cp.async.cg.shared.global [%0], [%1], 16;" :: "r"(dst), "l"(src) : "memory");
}
#define CP_COMMIT() asm volatile("cp.async.commit_group;" ::: "memory")
#define CP_WAIT(n)  asm volatile("cp.async.wait_group %0;" :: "n"(n) : "memory")

__device__ __forceinline__ void ldsm4(uint32_t& r0, uint32_t& r1, uint32_t& r2, uint32_t& r3, uint32_t addr) {
    asm volatile("ldmatrix.sync.aligned.m8n8.x4.shared.b16 {%0,%1,%2,%3}, [%4];"
        : "=r"(r0), "=r"(r1), "=r"(r2), "=r"(r3) : "r"(addr));
}
#define MMA16816(d, a, b0v, b1v) \
    asm volatile("mma.sync.aligned.m16n8k16.row.col.f32.bf16.bf16.f32 " \
        "{%0,%1,%2,%3}, {%4,%5,%6,%7}, {%8,%9}, {%0,%1,%2,%3};" \
        : "+f"((d)[0]), "+f"((d)[1]), "+f"((d)[2]), "+f"((d)[3]) \
        : "r"((a)[0]), "r"((a)[1]), "r"((a)[2]), "r"((a)[3]), "r"(b0v), "r"(b1v))

// ============================================================================
// Kernel 0: merged prep — transpose+split W_o and pack Wcat / bias-init T
// ============================================================================
#define TSP_BLOCKS 4352   // (OUT_/32) * (CONC/32) = 64*68
#define PACK_ELEMS (IN_ * NC + B_ * NC)
#define PACK_BLOCKS ((PACK_ELEMS + 255) / 256)

__global__ __launch_bounds__(256) void prep_kernel(
    const float* __restrict__ Wo,
    const float* __restrict__ W_ar, const float* __restrict__ b_ar,
    const float* __restrict__ W_f,  const float* __restrict__ b_f,
    const float* __restrict__ W_r,  const float* __restrict__ b_r)
{
    int bx = blockIdx.x;
    if (bx < TSP_BLOCKS) {
        __shared__ float tile[32][33];
        int n0 = (bx & 63) * 32, k0 = (bx >> 6) * 32;   // bx>>6 in 0..67
        int tx = threadIdx.x & 31, ty = threadIdx.x >> 5;
        #pragma unroll
        for (int dy = 0; dy < 4; dy++) {
            int k = k0 + ty * 4 + dy;
            tile[ty * 4 + dy][tx] = Wo[(size_t)k * OUT_ + n0 + tx];
        }
        __syncthreads();
        #pragma unroll
        for (int dy = 0; dy < 4; dy++) {
            int n = n0 + ty * 4 + dy;
            int k = k0 + tx;
            float v = tile[tx][ty * 4 + dy];
            __nv_bfloat16 h = __float2bfloat16(v);
            g_Bh[(size_t)n * CONC + k] = h;
            g_Bl[(size_t)n * CONC + k] = __float2bfloat16(v - __bfloat162float(h));
        }
    } else {
        int i = (bx - TSP_BLOCKS) * 256 + threadIdx.x;
        const int NW = IN_ * NC;
        if (i < NW) {
            int k = i / NC, j = i - k * NC;
            float v;
            if (j < 64)       v = W_ar[k * 64 + j];
            else if (j == 64) v = W_f[k];
            else              v = W_r[k * 65 + (j - 65)];
            g_Wcat[i] = v;
        } else if (i < NW + B_ * NC) {
            int r = i - NW;
            int j = r % NC;
            float v;
            if (j < 64)       v = b_ar[j];
            else if (j == 64) v = b_f[0];
            else              v = b_r[j - 65];
            g_T[r] = v;
        }
    }
}

// ============================================================================
// Kernel 1: front GEMM  T += x @ Wcat  (split-K atomic) + x -> bf16 hi/lo
// bn==0 blocks also convert their 64-row x 256-col x tile into g_Ah/g_Al.
// ============================================================================
__global__ __launch_bounds__(256) void gemm1_kernel(const float* __restrict__ x)
{
    __shared__ float As[16][68];
    __shared__ float Bs[16][68];
    int t  = threadIdx.x;
    int tx = t & 15, ty = t >> 4;
    int bm0 = blockIdx.x * 64;
    int bn0 = blockIdx.y * 64;
    int k0b = blockIdx.z * 256;

    float acc[4][4] = {};

    for (int kt = 0; kt < 16; kt++) {
        int k0 = k0b + kt * 16;
        {
            int row = t >> 2, kq = t & 3;
            float4 v = *(const float4*)&x[(size_t)(bm0 + row) * IN_ + k0 + kq * 4];
            As[kq * 4 + 0][row] = v.x;
            As[kq * 4 + 1][row] = v.y;
            As[kq * 4 + 2][row] = v.z;
            As[kq * 4 + 3][row] = v.w;
        }
        {
            int kr = t >> 4, cq = t & 15;
            #pragma unroll
            for (int j = 0; j < 4; j++) {
                int col = bn0 + cq * 4 + j;
                Bs[kr][cq * 4 + j] = (col < NC) ? g_Wcat[(size_t)(k0 + kr) * NC + col] : 0.f;
            }
        }
        __syncthreads();
        #pragma unroll
        for (int k = 0; k < 16; k++) {
            float a0 = As[k][ty * 4 + 0], a1 = As[k][ty * 4 + 1];
            float a2 = As[k][ty * 4 + 2], a3 = As[k][ty * 4 + 3];
            float b0 = Bs[k][tx * 4 + 0], b1 = Bs[k][tx * 4 + 1];
            float b2 = Bs[k][tx * 4 + 2], b3 = Bs[k][tx * 4 + 3];
            acc[0][0] += a0 * b0; acc[0][1] += a0 * b1; acc[0][2] += a0 * b2; acc[0][3] += a0 * b3;
            acc[1][0] += a1 * b0; acc[1][1] += a1 * b1; acc[1][2] += a1 * b2; acc[1][3] += a1 * b3;
            acc[2][0] += a2 * b0; acc[2][1] += a2 * b1; acc[2][2] += a2 * b2; acc[2][3] += a2 * b3;
            acc[3][0] += a3 * b0; acc[3][1] += a3 * b1; acc[3][2] += a3 * b2; acc[3][3] += a3 * b3;
        }
        __syncthreads();
    }
    #pragma unroll
    for (int i = 0; i < 4; i++) {
        int row = bm0 + ty * 4 + i;
        #pragma unroll
        for (int j = 0; j < 4; j++) {
            int col = bn0 + tx * 4 + j;
            if (col < NC) atomicAdd(&g_T[(size_t)row * NC + col], acc[i][j]);
        }
    }

    // x -> bf16 hi/lo for this block's (64 rows x 256 cols) tile, bn==0 only
    if (blockIdx.y == 0) {
        for (int i = t; i < 4096; i += 256) {          // 64 rows x 64 float4
            int row = i >> 6, c4 = i & 63;
            float4 v = *(const float4*)&x[(size_t)(bm0 + row) * IN_ + k0b + c4 * 4];
            size_t o = (size_t)(bm0 + row) * CONC + k0b + c4 * 4;
            __nv_bfloat16 h;
            h = __float2bfloat16(v.x); g_Ah[o + 0] = h; g_Al[o + 0] = __float2bfloat16(v.x - __bfloat162float(h));
            h = __float2bfloat16(v.y); g_Ah[o + 1] = h; g_Al[o + 1] = __float2bfloat16(v.y - __bfloat162float(h));
            h = __float2bfloat16(v.z); g_Ah[o + 2] = h; g_Al[o + 2] = __float2bfloat16(v.z - __bfloat162float(h));
            h = __float2bfloat16(v.w); g_Ah[o + 3] = h; g_Al[o + 3] = __float2bfloat16(v.w - __bfloat162float(h));
        }
    }
}

// ============================================================================
// Shared GEMM body: BM=64, BN=64, BK=32, 256 threads (8 warps: 2M x 4N),
// 2-stage cp.async pipeline. K-range [KB0, KB0+nkt*32), partial -> P.
// ============================================================================
#define PITCH_B  80
#define TILE_SZB (64 * PITCH_B)       // 5120
#define STAGE_SZ (4 * TILE_SZB)       // 20480
#define GEMM_SMEM (2 * STAGE_SZ)      // 40960

__device__ __forceinline__ void gemm_body(char* smem, int t, int bm0, int bn0,
                                          int KB0, int nkt, float* __restrict__ P)
{
    uint32_t sb = smem_u32(smem);
    int wid = t >> 5, lane = t & 31;

    // per-thread load mapping: 4 chunks of 16B per stage
    const __nv_bfloat16* gp[4];
    uint32_t sp[4];
    {
        const __nv_bfloat16* tb[4] = {
            g_Ah + (size_t)bm0 * CONC + KB0, g_Al + (size_t)bm0 * CONC + KB0,
            g_Bh + (size_t)bn0 * CONC + KB0, g_Bl + (size_t)bn0 * CONC + KB0 };
        #pragma unroll
        for (int j = 0; j < 4; j++) {
            int idx = t + j * 256;
            int tile = idx >> 8, wc = idx & 255;
            int r = wc >> 2, c = wc & 3;
            gp[j] = tb[tile] + (size_t)r * CONC + c * 8;
            sp[j] = (uint32_t)(tile * TILE_SZB + r * PITCH_B + c * 16);
        }
    }

    // warp tile: wm 0..1 (32 rows), wn 0..3 (16 cols)
    int wm = wid & 1, wn = wid >> 1;
    uint32_t aoff[2], boff;
    {
        int lr = lane & 15, lc = (lane >> 4) * 16;
        #pragma unroll
        for (int a = 0; a < 2; a++)
            aoff[a] = (uint32_t)((wm * 32 + a * 16 + lr) * PITCH_B + lc);
        boff = (uint32_t)((wn * 16 + lr) * PITCH_B + lc);
    }

    float acc[2][2][4];
    #pragma unroll
    for (int a = 0; a < 2; a++)
        #pragma unroll
        for (int g = 0; g < 2; g++)
            #pragma unroll
            for (int i = 0; i < 4; i++) acc[a][g][i] = 0.f;

    // prologue: stage 0 = k-tile 0
    #pragma unroll
    for (int j = 0; j < 4; j++) cp16(sb + sp[j], gp[j]);
    CP_COMMIT();

    for (int kt = 0; kt < nkt; kt++) {
        CP_WAIT(0);
        __syncthreads();

        if (kt + 1 < nkt) {
            uint32_t stb = sb + (uint32_t)((kt + 1) & 1) * STAGE_SZ;
            const int ko = (kt + 1) * 32;
            #pragma unroll
            for (int j = 0; j < 4; j++) cp16(stb + sp[j], gp[j] + ko);
            CP_COMMIT();
        }

        uint32_t stb = sb + (uint32_t)(kt & 1) * STAGE_SZ;
        uint32_t sA_h = stb, sA_l = stb + TILE_SZB;
        uint32_t sB_h = stb + 2 * TILE_SZB, sB_l = stb + 3 * TILE_SZB;

        #pragma unroll
        for (int ks = 0; ks < 2; ks++) {
            uint32_t kb = ks * 32;
            uint32_t ah[2][4], al[2][4], bh[4], bl[4];
            #pragma unroll
            for (int a = 0; a < 2; a++) {
                ldsm4(ah[a][0], ah[a][1], ah[a][2], ah[a][3], sA_h + aoff[a] + kb);
                ldsm4(al[a][0], al[a][1], al[a][2], al[a][3], sA_l + aoff[a] + kb);
            }
            ldsm4(bh[0], bh[1], bh[2], bh[3], sB_h + boff + kb);
            ldsm4(bl[0], bl[1], bl[2], bl[3], sB_l + boff + kb);
            #pragma unroll
            for (int a = 0; a < 2; a++) {
                MMA16816(acc[a][0], ah[a], bh[0], bh[2]);
                MMA16816(acc[a][1], ah[a], bh[1], bh[3]);
            }
            #pragma unroll
            for (int a = 0; a < 2; a++) {
                MMA16816(acc[a][0], al[a], bh[0], bh[2]);
                MMA16816(acc[a][1], al[a], bh[1], bh[3]);
            }
            #pragma unroll
            for (int a = 0; a < 2; a++) {
                MMA16816(acc[a][0], ah[a], bl[0], bl[2]);
                MMA16816(acc[a][1], ah[a], bl[1], bl[3]);
            }
        }
    }

    // epilogue: store partial
    int lr = lane >> 2, lc2 = (lane & 3) * 2;
    #pragma unroll
    for (int a = 0; a < 2; a++) {
        int row = bm0 + wm * 32 + a * 16 + lr;
        #pragma unroll
        for (int g = 0; g < 2; g++) {
            int col = bn0 + wn * 16 + g * 8 + lc2;
            *(float2*)&P[(size_t)row * OUT_ + col] = make_float2(acc[a][g][0], acc[a][g][1]);
            *(float2*)&P[(size_t)(row + 8) * OUT_ + col] = make_float2(acc[a][g][2], acc[a][g][3]);
        }
    }
}

// ============================================================================
// Kernel 2 (MEGA): blocks 0..511 = fused attention/memory-update per batch;
// blocks 512..1023 = main GEMM over K=[0,2048) (x part only), split-K=2.
// The two workloads are independent and co-scheduled for resource overlap.
// ============================================================================
#define PIT   68
#define FUSED_SMEM_FLOATS (128*PIT + 64*PIT + 64*3 + PIT + 128*4 + 8)
#define FUSED_SMEM_BYTES  (FUSED_SMEM_FLOATS * 4)
#define MEGA_SMEM (FUSED_SMEM_BYTES > GEMM_SMEM ? FUSED_SMEM_BYTES : GEMM_SMEM)

__global__ __launch_bounds__(256) void mega_kernel(
    const float* __restrict__ x, const float* __restrict__ memory,
    const float* __restrict__ W_pr, const float* __restrict__ b_pr,
    const float* __restrict__ W_f,  const float* __restrict__ W_r,
    float* __restrict__ new_mem)
{
    extern __shared__ char smraw[];
    int t = threadIdx.x;

    if (blockIdx.x >= B_) {
        // ---- main GEMM branch: 512 blocks = 8 bm x 32 bn x 2 kz ----
        int bid = blockIdx.x - B_;
        int kz  = bid >> 8;            // 0..1
        int r   = bid & 255;
        int bmi = r >> 5;              // 0..7
        int bni = r & 31;              // 0..31
        gemm_body(smraw, t, bmi * 64, bni * 64, kz * 1024, 32,
                  g_Cp + (size_t)kz * (B_ * OUT_));
        return;
    }

    // ---- fused branch ----
    float* sm = (float*)smraw;
    float* mem_s = sm;                        // [128][68]
    float* wrb_s = sm + 128 * PIT;            // [64][68]
    float* q_s   = wrb_s + 64 * PIT;          // 64
    float* wpr_s = q_s + 64;                  // 64
    float* wfb_s = wpr_s + 64;                // 64
    float* rx_s  = wfb_s + 64;                // 68 (65 used)
    float* sc_s  = rx_s + PIT;                // 128
    float* ps_s  = sc_s + 128;                // 128
    float* f_s   = ps_s + 128;                // 128
    float* g_s   = f_s + 128;                 // 128
    float* red   = g_s + 128;                 // 8

    int b = blockIdx.x;
    const float* mg = memory + (size_t)b * (NSLOT * MEMD);
    size_t abase = (size_t)b * CONC;

    // float4 memory-tile load
    for (int i = t; i < 2048; i += 256) {
        int row = i >> 4, c4 = i & 15;
        float4 v = *(const float4*)&mg[row * 64 + c4 * 4];
        *(float4*)&mem_s[row * PIT + c4 * 4] = v;
    }
    for (int i = t; i < 64 * 65; i += 256) {
        int r = i / 65, c = i - r * 65;
        wrb_s[r * PIT + c] = W_r[IN_ * 65 + i];
    }
    if (t < 64) {
        q_s[t]   = g_T[(size_t)b * NC + t];
        wpr_s[t] = W_pr[t];
        wfb_s[t] = W_f[IN_ + t];
    }
    if (t < 65) rx_s[t] = g_T[(size_t)b * NC + 65 + t];
    if (t == 0) { red[6] = g_T[(size_t)b * NC + 64]; red[7] = b_pr[0]; }
    __syncthreads();

    if (t < NSLOT) {
        const float4* mr4 = (const float4*)(mem_s + t * PIT);
        float s = 0.f, p = 0.f, f = 0.f, g = 0.f;
        #pragma unroll 4
        for (int k4 = 0; k4 < 16; k4++) {
            float4 mv = mr4[k4];
            int k = k4 * 4;
            s += mv.x * q_s[k]   + mv.y * q_s[k+1]   + mv.z * q_s[k+2]   + mv.w * q_s[k+3];
            p += mv.x * wpr_s[k] + mv.y * wpr_s[k+1] + mv.z * wpr_s[k+2] + mv.w * wpr_s[k+3];
            f += mv.x * wfb_s[k] + mv.y * wfb_s[k+1] + mv.z * wfb_s[k+2] + mv.w * wfb_s[k+3];
            g += mv.x * wrb_s[k * PIT + 64]       + mv.y * wrb_s[(k+1) * PIT + 64]
               + mv.z * wrb_s[(k+2) * PIT + 64]   + mv.w * wrb_s[(k+3) * PIT + 64];
        }
        sc_s[t] = s;
        ps_s[t] = p + red[7];
        f_s[t]  = 1.1f / (1.f + expf(-(f + red[6])));
        g_s[t]  = g + rx_s[64];
    }
    __syncthreads();

    if (t < 32) {
        float m1 = -1e30f, m2 = -1e30f;
        for (int i = t; i < 128; i += 32) { m1 = fmaxf(m1, sc_s[i]); m2 = fmaxf(m2, ps_s[i]); }
        #pragma unroll
        for (int o = 16; o; o >>= 1) {
            m1 = fmaxf(m1, __shfl_xor_sync(0xffffffffu, m1, o));
            m2 = fmaxf(m2, __shfl_xor_sync(0xffffffffu, m2, o));
        }
        if (t == 0) { red[0] = m1; red[1] = m2; }
    }
    __syncthreads();
    if (t < 128) { sc_s[t] = expf(sc_s[t] - red[0]); ps_s[t] = expf(ps_s[t] - red[1]); }
    __syncthreads();
    if (t < 32) {
        float s1 = 0.f, s2 = 0.f;
        for (int i = t; i < 128; i += 32) { s1 += sc_s[i]; s2 += ps_s[i]; }
        #pragma unroll
        for (int o = 16; o; o >>= 1) {
            s1 += __shfl_xor_sync(0xffffffffu, s1, o);
            s2 += __shfl_xor_sync(0xffffffffu, s2, o);
        }
        if (t == 0) { red[2] = 1.f / s1; red[3] = 1.f / s2; }
    }
    __syncthreads();

    if (t < 64) {
        float a = 0.f, pv = 0.f;
        #pragma unroll 8
        for (int n = 0; n < 128; n++) {
            float mv = mem_s[n * PIT + t];
            a  += mv * sc_s[n];
            pv += mv * ps_s[n];
        }
        a *= red[2]; pv *= red[3];
        __nv_bfloat16 ah = __float2bfloat16(a);
        g_Ah[abase + IN_ + t] = ah;
        g_Al[abase + IN_ + t] = __float2bfloat16(a - __bfloat162float(ah));
        __nv_bfloat16 ph = __float2bfloat16(pv);
        g_Ah[abase + IN_ + 64 + t] = ph;
        g_Al[abase + IN_ + 64 + t] = __float2bfloat16(pv - __bfloat162float(ph));
    }

    // memory update (float4 + f32x2)
    for (int tile = t; tile < 512; tile += 256) {
        int n0 = (tile >> 4) * 4;
        int m0 = (tile & 15) * 4;
        u64t acc2[4][2] = {{0ull, 0ull}, {0ull, 0ull}, {0ull, 0ull}, {0ull, 0ull}};
        const float* mp = mem_s + n0 * PIT;
        const float* wb = wrb_s + m0;
        #pragma unroll 2
        for (int k4 = 0; k4 < 16; k4++) {
            u64t bp[4][2];
            #pragma unroll
            for (int kk = 0; kk < 4; kk++) {
                float4 bv = *(const float4*)&wb[(k4 * 4 + kk) * PIT];
                bp[kk][0] = pk2(bv.x, bv.y);
                bp[kk][1] = pk2(bv.z, bv.w);
            }
            #pragma unroll
            for (int i = 0; i < 4; i++) {
                float4 av = *(const float4*)&mp[i * PIT + k4 * 4];
                u64t a0 = pk2(av.x, av.x);
                fma2(acc2[i][0], a0, bp[0][0]); fma2(acc2[i][1], a0, bp[0][1]);
                u64t a1 = pk2(av.y, av.y);
                fma2(acc2[i][0], a1, bp[1][0]); fma2(acc2[i][1], a1, bp[1][1]);
                u64t a2 = pk2(av.z, av.z);
                fma2(acc2[i][0], a2, bp[2][0]); fma2(acc2[i][1], a2, bp[2][1]);
                u64t a3 = pk2(av.w, av.w);
                fma2(acc2[i][0], a3, bp[3][0]); fma2(acc2[i][1], a3, bp[3][1]);
            }
        }
        #pragma unroll
        for (int i = 0; i < 4; i++) {
            int n = n0 + i;
            float fg = f_s[n], gg = g_s[n];
            const float* mr = mem_s + n * PIT;
            float2 v0 = upk2(acc2[i][0]);
            float2 v1 = upk2(acc2[i][1]);
            float4 o;
            o.x = mr[m0 + 0] * fg + gg * (rx_s[m0 + 0] + v0.x);
            o.y = mr[m0 + 1] * fg + gg * (rx_s[m0 + 1] + v0.y);
            o.z = mr[m0 + 2] * fg + gg * (rx_s[m0 + 2] + v1.x);
            o.w = mr[m0 + 3] * fg + gg * (rx_s[m0 + 3] + v1.y);
            *(float4*)&new_mem[(size_t)b * (NSLOT * MEMD) + n * MEMD + m0] = o;
        }
    }
}

// ============================================================================
// Kernel 3: tail GEMM over K=[2048,2176) (recall columns) -> partial P2
// ============================================================================
__global__ __launch_bounds__(256) void gemm_tail_kernel()
{
    extern __shared__ char smraw[];
    int bmi = blockIdx.x, bni = blockIdx.y;
    gemm_body(smraw, threadIdx.x, bmi * 64, bni * 64, IN_, 4,
              g_Cp + (size_t)2 * (B_ * OUT_));
}

// ============================================================================
// Kernel 4: reduce 3 partials + bias -> out
// ============================================================================
__global__ __launch_bounds__(256) void reduce_bias_kernel(const float* __restrict__ bias,
                                                          float* __restrict__ out)
{
    int i = (blockIdx.x * 256 + threadIdx.x) * 4;
    float4 p0 = *(const float4*)&g_Cp[i];
    float4 p1 = *(const float4*)&g_Cp[(size_t)B_ * OUT_ + i];
    float4 p2 = *(const float4*)&g_Cp[(size_t)2 * B_ * OUT_ + i];
    int col = i & (OUT_ - 1);
    float4 bb = *(const float4*)&bias[col];
    float4 o;
    o.x = p0.x + p1.x + p2.x + bb.x;
    o.y = p0.y + p1.y + p2.y + bb.y;
    o.z = p0.z + p1.z + p2.z + bb.z;
    o.w = p0.w + p1.w + p2.w + bb.w;
    *(float4*)&out[i] = o;
}

// ============================================================================
extern "C" void kernel_launch(void* const* d_in, const int* in_sizes, int n_in,
                              void* d_out, int out_size)
{
    const float* x      = (const float*)d_in[0];
    const float* memory = (const float*)d_in[1];
    const float* W_ar   = (const float*)d_in[2];
    const float* b_ar   = (const float*)d_in[3];
    const float* W_pr   = (const float*)d_in[4];
    const float* b_pr   = (const float*)d_in[5];
    const float* W_f    = (const float*)d_in[6];
    const float* b_f    = (const float*)d_in[7];
    const float* W_r    = (const float*)d_in[8];
    const float* b_r    = (const float*)d_in[9];
    const float* W_o    = (const float*)d_in[10];
    const float* b_o    = (const float*)d_in[11];

    float* out     = (float*)d_out;
    float* new_mem = out + (size_t)B_ * OUT_;

    cudaFuncSetAttribute(mega_kernel,
                         cudaFuncAttributeMaxDynamicSharedMemorySize, MEGA_SMEM);
    cudaFuncSetAttribute(gemm_tail_kernel,
                         cudaFuncAttributeMaxDynamicSharedMemorySize, GEMM_SMEM);

    // 0: merged prep (transpose+split W_o || pack Wcat + bias-init T)
    prep_kernel<<<TSP_BLOCKS + PACK_BLOCKS, 256>>>(W_o, W_ar, b_ar, W_f, b_f, W_r, b_r);
    // 1: front GEMM + x bf16 conversion
    {
        dim3 g(8, 3, 8);
        gemm1_kernel<<<g, 256>>>(x);
    }
    // 2: MEGA — fused (512 blocks) co-scheduled with main GEMM (512 blocks)
    mega_kernel<<<1024, 256, MEGA_SMEM>>>(x, memory, W_pr, b_pr, W_f, W_r, new_mem);
    // 3: tail GEMM over recall columns
    {
        dim3 g(8, 32);
        gemm_tail_kernel<<<g, 256, GEMM_SMEM>>>();
    }
    // 4: reduce + bias
    reduce_bias_kernel<<<(B_ * OUT_) / 1024, 256>>>(b_o, out);
}

// round 16
// speedup vs baseline: 1.2498x; 1.2498x over previous
#include <cuda_runtime.h>
#include <cuda_fp16.h>
#include <math.h>
#include <stdint.h>

// Problem dims
#define B_    512
#define NSLOT 128
#define IN_   2048
#define MEMD  64
#define OUT_  2048
#define NC    130
#define CONC  2176

// ---------------- scratch ----------------
__device__ float g_Wcat[IN_ * NC];
__device__ float g_T[B_ * NC];
__device__ __align__(256) __half g_Ah[B_ * CONC];    // interm hi (fp16)
__device__ __align__(256) __half g_Al[B_ * CONC];    // interm lo (fp16 residual)
__device__ __align__(256) __half g_Bh[OUT_ * CONC];  // W_o^T fp16 [N,K]
__device__ __align__(256) float g_Cp[2 * B_ * OUT_]; // split-K partials

// ---------------- helpers ----------------
typedef unsigned long long u64t;
__device__ __forceinline__ u64t pk2(float lo, float hi) {
    u64t r; asm("mov.b64 %0, {%1,%2};" : "=l"(r) : "f"(lo), "f"(hi)); return r;
}
__device__ __forceinline__ void fma2(u64t& d, u64t a, u64t b) {
    asm("fma.rn.f32x2 %0, %1, %2, %3;" : "=l"(d) : "l"(a), "l"(b), "l"(d));
}
__device__ __forceinline__ float2 upk2(u64t v) {
    float lo, hi; asm("mov.b64 {%0,%1}, %2;" : "=f"(lo), "=f"(hi) : "l"(v));
    return make_float2(lo, hi);
}
__device__ __forceinline__ uint32_t smem_u32(const void* p) {
    uint32_t a;
    asm("{ .reg .u64 t; cvta.to.shared.u64 t, %1; cvt.u32.u64 %0, t; }" : "=r"(a) : "l"(p));
    return a;
}
__device__ __forceinline__ void cp16(uint32_t dst, const void* src) {
    asm volatile("cp.async.cg.shared.global [%0], [%1], 16;" :: "r"(dst), "l"(src) : "memory");
}
#define CP_COMMIT() asm volatile("cp.async.commit_group;" ::: "memory")
#define CP_WAIT(n)  asm volatile("cp.async.wait_group %0;" :: "n"(n) : "memory")

__device__ __forceinline__ void ldsm4(uint32_t& r0, uint32_t& r1, uint32_t& r2, uint32_t& r3, uint32_t addr) {
    asm volatile("ldmatrix.sync.aligned.m8n8.x4.shared.b16 {%0,%1,%2,%3}, [%4];"
        : "=r"(r0), "=r"(r1), "=r"(r2), "=r"(r3) : "r"(addr));
}
#define MMA16816F(d, a, b0v, b1v) \
    asm volatile("mma.sync.aligned.m16n8k16.row.col.f32.f16.f16.f32 " \
        "{%0,%1,%2,%3}, {%4,%5,%6,%7}, {%8,%9}, {%0,%1,%2,%3};" \
        : "+f"((d)[0]), "+f"((d)[1]), "+f"((d)[2]), "+f"((d)[3]) \
        : "r"((a)[0]), "r"((a)[1]), "r"((a)[2]), "r"((a)[3]), "r"(b0v), "r"(b1v))

// ============================================================================
// Kernel 0: merged prep — transpose+fp16 W_o and pack Wcat / bias-init T
// ============================================================================
#define TSP_BLOCKS 4352   // (OUT_/32) * (CONC/32) = 64*68
#define PACK_ELEMS (IN_ * NC + B_ * NC)
#define PACK_BLOCKS ((PACK_ELEMS + 255) / 256)

__global__ __launch_bounds__(256) void prep_kernel(
    const float* __restrict__ Wo,
    const float* __restrict__ W_ar, const float* __restrict__ b_ar,
    const float* __restrict__ W_f,  const float* __restrict__ b_f,
    const float* __restrict__ W_r,  const float* __restrict__ b_r)
{
    int bx = blockIdx.x;
    if (bx < TSP_BLOCKS) {
        __shared__ float tile[32][33];
        int n0 = (bx & 63) * 32, k0 = (bx >> 6) * 32;   // bx>>6 in 0..67
        int tx = threadIdx.x & 31, ty = threadIdx.x >> 5;
        #pragma unroll
        for (int dy = 0; dy < 4; dy++) {
            int k = k0 + ty * 4 + dy;
            tile[ty * 4 + dy][tx] = Wo[(size_t)k * OUT_ + n0 + tx];
        }
        __syncthreads();
        #pragma unroll
        for (int dy = 0; dy < 4; dy++) {
            int n = n0 + ty * 4 + dy;
            int k = k0 + tx;
            g_Bh[(size_t)n * CONC + k] = __float2half_rn(tile[tx][ty * 4 + dy]);
        }
    } else {
        int i = (bx - TSP_BLOCKS) * 256 + threadIdx.x;
        const int NW = IN_ * NC;
        if (i < NW) {
            int k = i / NC, j = i - k * NC;
            float v;
            if (j < 64)       v = W_ar[k * 64 + j];
            else if (j == 64) v = W_f[k];
            else              v = W_r[k * 65 + (j - 65)];
            g_Wcat[i] = v;
        } else if (i < NW + B_ * NC) {
            int r = i - NW;
            int j = r % NC;
            float v;
            if (j < 64)       v = b_ar[j];
            else if (j == 64) v = b_f[0];
            else              v = b_r[j - 65];
            g_T[r] = v;
        }
    }
}

// ============================================================================
// Kernel 1: front GEMM  T += x[512,2048] @ Wcat[2048,130]   (split-K, atomic)
// ============================================================================
__global__ __launch_bounds__(256) void gemm1_kernel(const float* __restrict__ x)
{
    __shared__ float As[16][68];
    __shared__ float Bs[16][68];
    int t  = threadIdx.x;
    int tx = t & 15, ty = t >> 4;
    int bm0 = blockIdx.x * 64;
    int bn0 = blockIdx.y * 64;
    int k0b = blockIdx.z * 256;

    float acc[4][4] = {};

    for (int kt = 0; kt < 16; kt++) {
        int k0 = k0b + kt * 16;
        {
            int row = t >> 2, kq = t & 3;
            float4 v = *(const float4*)&x[(size_t)(bm0 + row) * IN_ + k0 + kq * 4];
            As[kq * 4 + 0][row] = v.x;
            As[kq * 4 + 1][row] = v.y;
            As[kq * 4 + 2][row] = v.z;
            As[kq * 4 + 3][row] = v.w;
        }
        {
            int kr = t >> 4, cq = t & 15;
            #pragma unroll
            for (int j = 0; j < 4; j++) {
                int col = bn0 + cq * 4 + j;
                Bs[kr][cq * 4 + j] = (col < NC) ? g_Wcat[(size_t)(k0 + kr) * NC + col] : 0.f;
            }
        }
        __syncthreads();
        #pragma unroll
        for (int k = 0; k < 16; k++) {
            float a0 = As[k][ty * 4 + 0], a1 = As[k][ty * 4 + 1];
            float a2 = As[k][ty * 4 + 2], a3 = As[k][ty * 4 + 3];
            float b0 = Bs[k][tx * 4 + 0], b1 = Bs[k][tx * 4 + 1];
            float b2 = Bs[k][tx * 4 + 2], b3 = Bs[k][tx * 4 + 3];
            acc[0][0] += a0 * b0; acc[0][1] += a0 * b1; acc[0][2] += a0 * b2; acc[0][3] += a0 * b3;
            acc[1][0] += a1 * b0; acc[1][1] += a1 * b1; acc[1][2] += a1 * b2; acc[1][3] += a1 * b3;
            acc[2][0] += a2 * b0; acc[2][1] += a2 * b1; acc[2][2] += a2 * b2; acc[2][3] += a2 * b3;
            acc[3][0] += a3 * b0; acc[3][1] += a3 * b1; acc[3][2] += a3 * b2; acc[3][3] += a3 * b3;
        }
        __syncthreads();
    }
    #pragma unroll
    for (int i = 0; i < 4; i++) {
        int row = bm0 + ty * 4 + i;
        #pragma unroll
        for (int j = 0; j < 4; j++) {
            int col = bn0 + tx * 4 + j;
            if (col < NC) atomicAdd(&g_T[(size_t)row * NC + col], acc[i][j]);
        }
    }
}

// ============================================================================
// Kernel 2: per-batch fused attention + softmax + recalls + memory update
// PIT=68 (16B-aligned rows); emits A as fp16 hi/lo.
// ============================================================================
#define PIT   68
#define FUSED_SMEM_FLOATS (128*PIT + 64*PIT + 64*3 + PIT + 128*4 + 8)
#define FUSED_SMEM_BYTES  (FUSED_SMEM_FLOATS * 4)

__global__ __launch_bounds__(256, 4) void fused_mem_kernel(
    const float* __restrict__ x, const float* __restrict__ memory,
    const float* __restrict__ W_pr, const float* __restrict__ b_pr,
    const float* __restrict__ W_f,  const float* __restrict__ W_r,
    float* __restrict__ new_mem)
{
    extern __shared__ float sm[];
    float* mem_s = sm;                        // [128][68]
    float* wrb_s = sm + 128 * PIT;            // [64][68]
    float* q_s   = wrb_s + 64 * PIT;          // 64
    float* wpr_s = q_s + 64;                  // 64
    float* wfb_s = wpr_s + 64;                // 64
    float* rx_s  = wfb_s + 64;                // 68 (65 used)
    float* sc_s  = rx_s + PIT;                // 128
    float* ps_s  = sc_s + 128;                // 128
    float* f_s   = ps_s + 128;                // 128
    float* g_s   = f_s + 128;                 // 128
    float* red   = g_s + 128;                 // 8

    int b = blockIdx.x, t = threadIdx.x;
    const float* mg = memory + (size_t)b * (NSLOT * MEMD);
    size_t abase = (size_t)b * CONC;

    for (int i = t; i < NSLOT * MEMD; i += 256)
        mem_s[(i >> 6) * PIT + (i & 63)] = mg[i];
    for (int i = t; i < 64 * 65; i += 256) {
        int r = i / 65, c = i - r * 65;
        wrb_s[r * PIT + c] = W_r[IN_ * 65 + i];
    }
    if (t < 64) {
        q_s[t]   = g_T[(size_t)b * NC + t];
        wpr_s[t] = W_pr[t];
        wfb_s[t] = W_f[IN_ + t];
    }
    if (t < 65) rx_s[t] = g_T[(size_t)b * NC + 65 + t];
    if (t == 0) { red[6] = g_T[(size_t)b * NC + 64]; red[7] = b_pr[0]; }

    // x row -> fp16 hi/lo (independent of smem)
    {
        const float* xr = x + (size_t)b * IN_;
        for (int i = t; i < IN_; i += 256) {
            float v = xr[i];
            __half h = __float2half_rn(v);
            g_Ah[abase + i] = h;
            g_Al[abase + i] = __float2half_rn(v - __half2float(h));
        }
    }
    __syncthreads();

    if (t < NSLOT) {
        const float4* mr4 = (const float4*)(mem_s + t * PIT);
        float s = 0.f, p = 0.f, f = 0.f, g = 0.f;
        #pragma unroll 4
        for (int k4 = 0; k4 < 16; k4++) {
            float4 mv = mr4[k4];
            int k = k4 * 4;
            s += mv.x * q_s[k]   + mv.y * q_s[k+1]   + mv.z * q_s[k+2]   + mv.w * q_s[k+3];
            p += mv.x * wpr_s[k] + mv.y * wpr_s[k+1] + mv.z * wpr_s[k+2] + mv.w * wpr_s[k+3];
            f += mv.x * wfb_s[k] + mv.y * wfb_s[k+1] + mv.z * wfb_s[k+2] + mv.w * wfb_s[k+3];
            g += mv.x * wrb_s[k * PIT + 64]       + mv.y * wrb_s[(k+1) * PIT + 64]
               + mv.z * wrb_s[(k+2) * PIT + 64]   + mv.w * wrb_s[(k+3) * PIT + 64];
        }
        sc_s[t] = s;
        ps_s[t] = p + red[7];
        f_s[t]  = 1.1f / (1.f + expf(-(f + red[6])));
        g_s[t]  = g + rx_s[64];
    }
    __syncthreads();

    if (t < 32) {
        float m1 = -1e30f, m2 = -1e30f;
        for (int i = t; i < 128; i += 32) { m1 = fmaxf(m1, sc_s[i]); m2 = fmaxf(m2, ps_s[i]); }
        #pragma unroll
        for (int o = 16; o; o >>= 1) {
            m1 = fmaxf(m1, __shfl_xor_sync(0xffffffffu, m1, o));
            m2 = fmaxf(m2, __shfl_xor_sync(0xffffffffu, m2, o));
        }
        if (t == 0) { red[0] = m1; red[1] = m2; }
    }
    __syncthreads();
    if (t < 128) { sc_s[t] = expf(sc_s[t] - red[0]); ps_s[t] = expf(ps_s[t] - red[1]); }
    __syncthreads();
    if (t < 32) {
        float s1 = 0.f, s2 = 0.f;
        for (int i = t; i < 128; i += 32) { s1 += sc_s[i]; s2 += ps_s[i]; }
        #pragma unroll
        for (int o = 16; o; o >>= 1) {
            s1 += __shfl_xor_sync(0xffffffffu, s1, o);
            s2 += __shfl_xor_sync(0xffffffffu, s2, o);
        }
        if (t == 0) { red[2] = 1.f / s1; red[3] = 1.f / s2; }
    }
    __syncthreads();

    if (t < 64) {
        float a = 0.f, pv = 0.f;
        #pragma unroll 8
        for (int n = 0; n < 128; n++) {
            float mv = mem_s[n * PIT + t];
            a  += mv * sc_s[n];
            pv += mv * ps_s[n];
        }
        a *= red[2]; pv *= red[3];
        __half ah = __float2half_rn(a);
        g_Ah[abase + IN_ + t] = ah;
        g_Al[abase + IN_ + t] = __float2half_rn(a - __half2float(ah));
        __half ph = __float2half_rn(pv);
        g_Ah[abase + IN_ + 64 + t] = ph;
        g_Al[abase + IN_ + 64 + t] = __float2half_rn(pv - __half2float(ph));
    }

    // memory update: new_mem = mem*forget + gate * (rx + mem @ Wr_bot)
    for (int tile = t; tile < 512; tile += 256) {
        int n0 = (tile >> 4) * 4;
        int m0 = (tile & 15) * 4;
        u64t acc2[4][2] = {{0ull, 0ull}, {0ull, 0ull}, {0ull, 0ull}, {0ull, 0ull}};
        const float* mp = mem_s + n0 * PIT;
        const float* wb = wrb_s + m0;
        #pragma unroll 2
        for (int k4 = 0; k4 < 16; k4++) {
            u64t bp[4][2];
            #pragma unroll
            for (int kk = 0; kk < 4; kk++) {
                float4 bv = *(const float4*)&wb[(k4 * 4 + kk) * PIT];
                bp[kk][0] = pk2(bv.x, bv.y);
                bp[kk][1] = pk2(bv.z, bv.w);
            }
            #pragma unroll
            for (int i = 0; i < 4; i++) {
                float4 av = *(const float4*)&mp[i * PIT + k4 * 4];
                u64t a0 = pk2(av.x, av.x);
                fma2(acc2[i][0], a0, bp[0][0]); fma2(acc2[i][1], a0, bp[0][1]);
                u64t a1 = pk2(av.y, av.y);
                fma2(acc2[i][0], a1, bp[1][0]); fma2(acc2[i][1], a1, bp[1][1]);
                u64t a2 = pk2(av.z, av.z);
                fma2(acc2[i][0], a2, bp[2][0]); fma2(acc2[i][1], a2, bp[2][1]);
                u64t a3 = pk2(av.w, av.w);
                fma2(acc2[i][0], a3, bp[3][0]); fma2(acc2[i][1], a3, bp[3][1]);
            }
        }
        #pragma unroll
        for (int i = 0; i < 4; i++) {
            int n = n0 + i;
            float fg = f_s[n], gg = g_s[n];
            const float* mr = mem_s + n * PIT;
            float2 v0 = upk2(acc2[i][0]);
            float2 v1 = upk2(acc2[i][1]);
            float4 o;
            o.x = mr[m0 + 0] * fg + gg * (rx_s[m0 + 0] + v0.x);
            o.y = mr[m0 + 1] * fg + gg * (rx_s[m0 + 1] + v0.y);
            o.z = mr[m0 + 2] * fg + gg * (rx_s[m0 + 2] + v1.x);
            o.w = mr[m0 + 3] * fg + gg * (rx_s[m0 + 3] + v1.y);
            *(float4*)&new_mem[(size_t)b * (NSLOT * MEMD) + n * MEMD + m0] = o;
        }
    }
}

// ============================================================================
// Kernel 3: output GEMM via mma.sync fp16 (2-term: Ah*B + Al*B), split-K=2
// BM=64, BN=64, BK=32, grid (8,32,2)=512 CTAs, 256 threads (8 warps: 2M x 4N)
// 3 tiles/stage {Ah, Al, Bh}; 2-stage cp.async pipeline, 1 sync per k-tile.
// ============================================================================
#define GKT_H    (CONC / 32 / 2)      // 34 k-tiles per half
#define PITCH_B  80
#define TILE_SZB (64 * PITCH_B)       // 5120
#define STAGE_SZ (3 * TILE_SZB)       // 15360
#define GO_SMEM  (2 * STAGE_SZ)       // 30720

__global__ __launch_bounds__(256) void gemm_out_mma_kernel()
{
    extern __shared__ char smem[];
    uint32_t sb = smem_u32(smem);
    int t = threadIdx.x;
    int wid = t >> 5, lane = t & 31;
    int bm0 = blockIdx.x * 64;
    int bn0 = blockIdx.y * 64;
    int kz  = blockIdx.z;
    const int KB0 = kz * GKT_H * 32;

    // ---- per-thread load mapping: 3 chunks of 16B per stage ----
    const __half* gp[3];
    uint32_t sp[3];
    {
        const __half* tb[3] = {
            g_Ah + (size_t)bm0 * CONC + KB0, g_Al + (size_t)bm0 * CONC + KB0,
            g_Bh + (size_t)bn0 * CONC + KB0 };
        #pragma unroll
        for (int j = 0; j < 3; j++) {
            int idx = t + j * 256;
            int tile = idx >> 8, wc = idx & 255;
            int r = wc >> 2, c = wc & 3;
            gp[j] = tb[tile] + (size_t)r * CONC + c * 8;
            sp[j] = (uint32_t)(tile * TILE_SZB + r * PITCH_B + c * 16);
        }
    }

    // ---- warp tile: wm 0..1 (32 rows), wn 0..3 (16 cols) ----
    int wm = wid & 1, wn = wid >> 1;
    uint32_t aoff[2], boff;
    {
        int lr = lane & 15, lc = (lane >> 4) * 16;
        #pragma unroll
        for (int a = 0; a < 2; a++)
            aoff[a] = (uint32_t)((wm * 32 + a * 16 + lr) * PITCH_B + lc);
        boff = (uint32_t)((wn * 16 + lr) * PITCH_B + lc);
    }

    float acc[2][2][4];
    #pragma unroll
    for (int a = 0; a < 2; a++)
        #pragma unroll
        for (int g = 0; g < 2; g++)
            #pragma unroll
            for (int i = 0; i < 4; i++) acc[a][g][i] = 0.f;

    // ---- prologue: stage 0 = k-tile 0 ----
    #pragma unroll
    for (int j = 0; j < 3; j++) cp16(sb + sp[j], gp[j]);
    CP_COMMIT();

    for (int kt = 0; kt < GKT_H; kt++) {
        CP_WAIT(0);            // k-tile kt landed (single group outstanding)
        __syncthreads();       // all warps finished reading the other stage

        if (kt + 1 < GKT_H) {  // issue kt+1 into the stage just freed
            uint32_t stb = sb + (uint32_t)((kt + 1) & 1) * STAGE_SZ;
            const int ko = (kt + 1) * 32;
            #pragma unroll
            for (int j = 0; j < 3; j++) cp16(stb + sp[j], gp[j] + ko);
            CP_COMMIT();
        }

        uint32_t stb = sb + (uint32_t)(kt & 1) * STAGE_SZ;
        uint32_t sA_h = stb, sA_l = stb + TILE_SZB, sB_h = stb + 2 * TILE_SZB;

        #pragma unroll
        for (int ks = 0; ks < 2; ks++) {
            uint32_t kb = ks * 32;
            uint32_t ah[2][4], al[2][4], bh[4];
            #pragma unroll
            for (int a = 0; a < 2; a++) {
                ldsm4(ah[a][0], ah[a][1], ah[a][2], ah[a][3], sA_h + aoff[a] + kb);
                ldsm4(al[a][0], al[a][1], al[a][2], al[a][3], sA_l + aoff[a] + kb);
            }
            ldsm4(bh[0], bh[1], bh[2], bh[3], sB_h + boff + kb);
            #pragma unroll
            for (int a = 0; a < 2; a++) {
                MMA16816F(acc[a][0], ah[a], bh[0], bh[2]);
                MMA16816F(acc[a][1], ah[a], bh[1], bh[3]);
            }
            #pragma unroll
            for (int a = 0; a < 2; a++) {
                MMA16816F(acc[a][0], al[a], bh[0], bh[2]);
                MMA16816F(acc[a][1], al[a], bh[1], bh[3]);
            }
        }
    }

    // ---- epilogue: store partial ----
    float* P = g_Cp + (size_t)kz * (B_ * OUT_);
    int lr = lane >> 2, lc2 = (lane & 3) * 2;
    #pragma unroll
    for (int a = 0; a < 2; a++) {
        int row = bm0 + wm * 32 + a * 16 + lr;
        #pragma unroll
        for (int g = 0; g < 2; g++) {
            int col = bn0 + wn * 16 + g * 8 + lc2;
            *(float2*)&P[(size_t)row * OUT_ + col] = make_float2(acc[a][g][0], acc[a][g][1]);
            *(float2*)&P[(size_t)(row + 8) * OUT_ + col] = make_float2(acc[a][g][2], acc[a][g][3]);
        }
    }
}

// ============================================================================
// Kernel 4: reduce partials + bias -> out
// ============================================================================
__global__ __launch_bounds__(256) void reduce_bias_kernel(const float* __restrict__ bias,
                                                          float* __restrict__ out)
{
    int i = (blockIdx.x * 256 + threadIdx.x) * 4;
    float4 p0 = *(const float4*)&g_Cp[i];
    float4 p1 = *(const float4*)&g_Cp[(size_t)B_ * OUT_ + i];
    int col = i & (OUT_ - 1);
    float4 bb = *(const float4*)&bias[col];
    float4 o;
    o.x = p0.x + p1.x + bb.x;
    o.y = p0.y + p1.y + bb.y;
    o.z = p0.z + p1.z + bb.z;
    o.w = p0.w + p1.w + bb.w;
    *(float4*)&out[i] = o;
}

// ============================================================================
extern "C" void kernel_launch(void* const* d_in, const int* in_sizes, int n_in,
                              void* d_out, int out_size)
{
    const float* x      = (const float*)d_in[0];
    const float* memory = (const float*)d_in[1];
    const float* W_ar   = (const float*)d_in[2];
    const float* b_ar   = (const float*)d_in[3];
    const float* W_pr   = (const float*)d_in[4];
    const float* b_pr   = (const float*)d_in[5];
    const float* W_f    = (const float*)d_in[6];
    const float* b_f    = (const float*)d_in[7];
    const float* W_r    = (const float*)d_in[8];
    const float* b_r    = (const float*)d_in[9];
    const float* W_o    = (const float*)d_in[10];
    const float* b_o    = (const float*)d_in[11];

    float* out     = (float*)d_out;
    float* new_mem = out + (size_t)B_ * OUT_;

    cudaFuncSetAttribute(fused_mem_kernel,
                         cudaFuncAttributeMaxDynamicSharedMemorySize, FUSED_SMEM_BYTES);
    cudaFuncSetAttribute(gemm_out_mma_kernel,
                         cudaFuncAttributeMaxDynamicSharedMemorySize, GO_SMEM);

    // 0: merged prep (transpose W_o -> fp16 || pack Wcat + bias-init T)
    prep_kernel<<<TSP_BLOCKS + PACK_BLOCKS, 256>>>(W_o, W_ar, b_ar, W_f, b_f, W_r, b_r);
    // 1: front GEMM
    {
        dim3 g(8, 3, 8);
        gemm1_kernel<<<g, 256>>>(x);
    }
    // 2: fused attention + recalls + memory update (emits A fp16 hi/lo)
    fused_mem_kernel<<<B_, 256, FUSED_SMEM_BYTES>>>(x, memory, W_pr, b_pr, W_f, W_r, new_mem);
    // 3: output GEMM (fp16 2-term), split-K=2, 512 CTAs
    {
        dim3 g(B_ / 64, OUT_ / 64, 2);
        gemm_out_mma_kernel<<<g, 256, GO_SMEM>>>();
    }
    // 4: reduce + bias
    reduce_bias_kernel<<<(B_ * OUT_) / 1024, 256>>>(b_o, out);
}